// round 11
// baseline (speedup 1.0000x reference)
#include <cuda_runtime.h>
#include <cuda_bf16.h>
#include <cstdint>

// Problem constants
#define NUM_CHIPS 4
#define SEQ 1024
#define HIDDEN 2048
#define TOP_K 4
#define N_EXPERTS 32
#define MAX_TOK 1024
#define META_LEN 8
#define N_PER_CHIP (SEQ * TOP_K)           // 4096
#define N_TOTAL (NUM_CHIPS * N_PER_CHIP)   // 16384 assignments
#define N_CHUNKS (N_TOTAL / 32)            // 512 warp-chunks, chip-major
#define TOTAL_SLOTS (N_EXPERTS * MAX_TOK)  // 32768
#define BUF_ELEMS ((size_t)TOTAL_SLOTS * HIDDEN)
#define META_OFF  BUF_ELEMS
#define CNT_OFF   (BUF_ELEMS + (size_t)TOTAL_SLOTS * META_LEN)

#define NB 444                  // persistent blocks (3/SM @512 thr -> co-resident, no deadlock)
#define THREADS 512
#define PLAN_BLOCKS 32          // blocks 0..31 plan 16 chunks each; block 32 emits totals

// Scratch (no allocations allowed). g_bar is MONOTONE across graph replays:
// exactly NB tickets consumed per replay -> window math is exact, no reset.
__device__ int g_src[TOTAL_SLOTS];   // slot -> assignment id (first cnt_e per expert valid)
__device__ int g_cnt[N_EXPERTS];     // per-expert totals
__device__ unsigned g_bar;           // monotone barrier tickets

__global__ void __launch_bounds__(THREADS) dispatch_kernel(
    const float* __restrict__ x, const float* __restrict__ w,
    const int* __restrict__ idx, float* __restrict__ out)
{
    __shared__ int s_hist[N_EXPERTS];        // histogram of preceding region
    __shared__ int s_cnt[16][N_EXPERTS];     // per-warp per-expert counts (this block)
    __shared__ int s_pref[N_EXPERTS][16];    // exclusive warp prefix per expert
    __shared__ unsigned s_target;

    const int warp = threadIdx.x >> 5;       // 0..15
    const int lane = threadIdx.x & 31;
    const unsigned lt = (1u << lane) - 1u;
    const int b = blockIdx.x;

    // ---------------- Phase 1: planning (blocks 0..32), barrier-free -------
    if (b <= PLAN_BLOCKS) {
        if (threadIdx.x < N_EXPERTS) s_hist[threadIdx.x] = 0;
        s_cnt[warp][lane] = 0;
        __syncthreads();

        if (b == PLAN_BLOCKS) {
            // Totals block: histogram ALL 512 chunks.
            for (int ch = warp; ch < N_CHUNKS; ch += 16) {
                const int e = __ldg(&idx[ch * 32 + lane]);
                const unsigned m = __match_any_sync(0xFFFFFFFFu, e);
                if ((m & lt) == 0) atomicAdd(&s_hist[e], __popc(m));
            }
            __syncthreads();
            if (threadIdx.x < N_EXPERTS) {
                g_cnt[threadIdx.x] = s_hist[threadIdx.x];
                out[CNT_OFF + threadIdx.x] = (float)s_hist[threadIdx.x];
            }
        } else {
            // Own chunk (warp w owns chunk b*16+w): rank + per-warp counts.
            const int a = (b * 16 + warp) * 32 + lane;
            const int e = __ldg(&idx[a]);
            const unsigned m = __match_any_sync(0xFFFFFFFFu, e);
            const int rk = __popc(m & lt);
            if (rk == 0) s_cnt[warp][e] = __popc(m);  // leaders: distinct e, no conflict

            // Redundant histogram of preceding chunks [0, b*16).
            for (int ch = warp; ch < b * 16; ch += 16) {
                const int pe = __ldg(&idx[ch * 32 + lane]);
                const unsigned pm = __match_any_sync(0xFFFFFFFFu, pe);
                if ((pm & lt) == 0) atomicAdd(&s_hist[pe], __popc(pm));
            }
            __syncthreads();

            // Exclusive prefix over the 16 warps, per expert.
            // Thread t handles (expert = t>>4, warp-index = t&15); width-16 scan.
            {
                const int e2 = threadIdx.x >> 4;
                const int wi = threadIdx.x & 15;
                const int c  = s_cnt[wi][e2];
                int s = c;
#pragma unroll
                for (int d = 1; d < 16; d <<= 1) {
                    int t = __shfl_up_sync(0xFFFFFFFFu, s, d, 16);
                    if (wi >= d) s += t;
                }
                s_pref[e2][wi] = s - c;
            }
            __syncthreads();

            // Emit inverse map.
            const int slot = e * MAX_TOK + s_hist[e] + s_pref[e][warp] + rk;
            g_src[slot] = a;
        }
    }

    // ---------------- One monotone-window grid barrier (all NB blocks) -----
    __syncthreads();
    __threadfence();
    if (threadIdx.x == 0) {
        const unsigned t = atomicAdd(&g_bar, 1u);
        const unsigned target = (t / NB + 1u) * NB;   // exactly NB tickets per replay
        s_target = target;
        while (atomicAdd(&g_bar, 0u) < target) { }
    }
    __syncthreads();
    __threadfence();

    // ---------------- Phase 2: gather (all blocks, persistent loop) --------
    const int t = threadIdx.x;
    for (int slot = b; slot < TOTAL_SLOTS; slot += NB) {
        const int e  = slot >> 10;
        const int si = slot & (MAX_TOK - 1);
        float4* dst = reinterpret_cast<float4*>(out + (size_t)slot * HIDDEN);
        float4* md  = reinterpret_cast<float4*>(out + META_OFF + (size_t)slot * META_LEN);

        if (si < g_cnt[e]) {
            const int a   = g_src[slot];
            const int c   = a >> 12;
            const int n   = a & (N_PER_CHIP - 1);
            const int tok = n >> 2;
            const float4* src =
                reinterpret_cast<const float4*>(x + ((size_t)c * SEQ + tok) * HIDDEN);
            dst[t] = src[t];                       // 512 threads x 16B = 8KB row
            if (t == 0) {
                __nv_bfloat16 hb = __float2bfloat16(w[a]);
                unsigned short bits = __bfloat16_as_ushort(hb);
                md[0] = make_float4((float)c, (float)tok, (float)(n & 3), (float)e);
                md[1] = make_float4((float)bits, 0.f, 0.f, 0.f);
            }
        } else {
            dst[t] = make_float4(0.f, 0.f, 0.f, 0.f);
            if (t == 0) {
                const float4 neg = make_float4(-1.f, -1.f, -1.f, -1.f);
                md[0] = neg;
                md[1] = neg;
            }
        }
    }
    (void)s_target;
}

// ---------------------------------------------------------------------------
extern "C" void kernel_launch(void* const* d_in, const int* in_sizes, int n_in,
                              void* d_out, int out_size) {
    const float* x   = (const float*)d_in[0];   // [4,1024,2048] f32
    const float* wts = (const float*)d_in[1];   // [4,1024,4]    f32
    const int*   ind = (const int*)  d_in[2];   // [4,1024,4]    i32
    float* out = (float*)d_out;

    dispatch_kernel<<<NB, THREADS>>>(x, wts, ind, out);
}

// round 12
// speedup vs baseline: 1.0082x; 1.0082x over previous
#include <cuda_runtime.h>
#include <cuda_bf16.h>
#include <cstdint>

// Problem constants
#define NUM_CHIPS 4
#define SEQ 1024
#define HIDDEN 2048
#define TOP_K 4
#define N_EXPERTS 32
#define MAX_TOK 1024
#define META_LEN 8
#define N_PER_CHIP (SEQ * TOP_K)           // 4096
#define N_TOTAL (NUM_CHIPS * N_PER_CHIP)   // 16384 assignments
#define N_CHUNKS (N_TOTAL / 32)            // 512 warp-chunks, chip-major
#define TOTAL_SLOTS (N_EXPERTS * MAX_TOK)  // 32768
#define BUF_ELEMS ((size_t)TOTAL_SLOTS * HIDDEN)
#define META_OFF  BUF_ELEMS
#define CNT_OFF   (BUF_ELEMS + (size_t)TOTAL_SLOTS * META_LEN)

#define NB 444                  // persistent blocks: 3/SM @ 512 thr -> fully co-resident
#define THREADS 512
#define PLAN_BLOCKS 32          // blocks 0..31 plan 16 chunks each; block 32 emits totals
#define X_FLOAT4 ((NUM_CHIPS * SEQ * HIDDEN) / 4)   // 2M float4 = 32 MB

// Scratch (no allocations allowed). g_bar is MONOTONE across graph replays:
// exactly NB tickets per replay -> window math exact, no reset kernel.
__device__ int g_src[TOTAL_SLOTS];   // slot -> assignment id (first cnt_e per expert valid)
__device__ int g_cnt[N_EXPERTS];     // per-expert totals
__device__ unsigned g_bar;           // monotone barrier tickets
__device__ float g_sink;             // DCE-blocker for the L2 warm loop (never read)

__global__ void __launch_bounds__(THREADS, 3) dispatch_kernel(
    const float* __restrict__ x, const float* __restrict__ w,
    const int* __restrict__ idx, float* __restrict__ out)
{
    __shared__ int s_hist[N_EXPERTS];        // histogram of preceding region
    __shared__ int s_cnt[16][N_EXPERTS];     // per-warp per-expert counts (this block)
    __shared__ int s_pref[N_EXPERTS][16];    // exclusive warp prefix per expert

    const int warp = threadIdx.x >> 5;       // 0..15
    const int lane = threadIdx.x & 31;
    const unsigned lt = (1u << lane) - 1u;
    const int b = blockIdx.x;

    // ---------------- Phase 1a: planning (blocks 0..32), barrier-free ------
    if (b <= PLAN_BLOCKS) {
        if (threadIdx.x < N_EXPERTS) s_hist[threadIdx.x] = 0;
        s_cnt[warp][lane] = 0;
        __syncthreads();

        if (b == PLAN_BLOCKS) {
            // Totals block: histogram ALL 512 chunks.
#pragma unroll 4
            for (int ch = warp; ch < N_CHUNKS; ch += 16) {
                const int e = __ldg(&idx[ch * 32 + lane]);
                const unsigned m = __match_any_sync(0xFFFFFFFFu, e);
                if ((m & lt) == 0) atomicAdd(&s_hist[e], __popc(m));
            }
            __syncthreads();
            if (threadIdx.x < N_EXPERTS) {
                g_cnt[threadIdx.x] = s_hist[threadIdx.x];
                out[CNT_OFF + threadIdx.x] = (float)s_hist[threadIdx.x];
            }
        } else {
            // Own chunk (warp w owns chunk b*16+w): rank + per-warp counts.
            const int a = (b * 16 + warp) * 32 + lane;
            const int e = __ldg(&idx[a]);
            const unsigned m = __match_any_sync(0xFFFFFFFFu, e);
            const int rk = __popc(m & lt);
            if (rk == 0) s_cnt[warp][e] = __popc(m);  // leaders: distinct e, no conflict

            // Redundant histogram of preceding chunks [0, b*16); unrolled for MLP.
#pragma unroll 4
            for (int ch = warp; ch < b * 16; ch += 16) {
                const int pe = __ldg(&idx[ch * 32 + lane]);
                const unsigned pm = __match_any_sync(0xFFFFFFFFu, pe);
                if ((pm & lt) == 0) atomicAdd(&s_hist[pe], __popc(pm));
            }
            __syncthreads();

            // Exclusive prefix over the 16 warps, per expert (width-16 scans).
            {
                const int e2 = threadIdx.x >> 4;
                const int wi = threadIdx.x & 15;
                const int c  = s_cnt[wi][e2];
                int s = c;
#pragma unroll
                for (int d = 1; d < 16; d <<= 1) {
                    int t = __shfl_up_sync(0xFFFFFFFFu, s, d, 16);
                    if (wi >= d) s += t;
                }
                s_pref[e2][wi] = s - c;
            }
            __syncthreads();

            // Emit inverse map.
            const int slot = e * MAX_TOK + s_hist[e] + s_pref[e][warp] + rk;
            g_src[slot] = a;
        }
    } else {
        // ---------------- Phase 1b: L2 warm (blocks 33..443) ---------------
        // While planners work, pull all of x (32 MB) into L2 so the gather
        // phase is a nearly pure write stream. Result folded into a sink that
        // is (practically) never written, blocking DCE.
        const int nwarm = NB - PLAN_BLOCKS - 1;                 // 411 blocks
        const int wb = b - PLAN_BLOCKS - 1;                     // 0..410
        const float4* xv = reinterpret_cast<const float4*>(x);
        float acc = 0.f;
        for (int i = wb * THREADS + threadIdx.x; i < X_FLOAT4; i += nwarm * THREADS) {
            const float4 v = xv[i];
            acc += v.x + v.y + v.z + v.w;
        }
        if (acc == 1.2345e-38f) g_sink = acc;   // never true in practice; never read
    }

    // ---------------- One monotone-window grid barrier ---------------------
    __syncthreads();
    __threadfence();
    if (threadIdx.x == 0) {
        const unsigned t = atomicAdd(&g_bar, 1u);
        const unsigned target = (t / NB + 1u) * NB;   // exactly NB tickets per replay
        while (atomicAdd(&g_bar, 0u) < target) { }
    }
    __syncthreads();
    __threadfence();

    // ---------------- Phase 2: gather (all blocks, persistent loop) --------
    const int t = threadIdx.x;
    for (int slot = b; slot < TOTAL_SLOTS; slot += NB) {
        const int e  = slot >> 10;
        const int si = slot & (MAX_TOK - 1);
        float4* dst = reinterpret_cast<float4*>(out + (size_t)slot * HIDDEN);
        float4* md  = reinterpret_cast<float4*>(out + META_OFF + (size_t)slot * META_LEN);

        if (si < g_cnt[e]) {
            const int a   = g_src[slot];
            const int c   = a >> 12;
            const int n   = a & (N_PER_CHIP - 1);
            const int tok = n >> 2;
            const float4* src =
                reinterpret_cast<const float4*>(x + ((size_t)c * SEQ + tok) * HIDDEN);
            dst[t] = src[t];                       // 512 threads x 16B = 8KB row
            if (t == 0) {
                __nv_bfloat16 hb = __float2bfloat16(w[a]);
                unsigned short bits = __bfloat16_as_ushort(hb);
                md[0] = make_float4((float)c, (float)tok, (float)(n & 3), (float)e);
                md[1] = make_float4((float)bits, 0.f, 0.f, 0.f);
            }
        } else {
            dst[t] = make_float4(0.f, 0.f, 0.f, 0.f);
            if (t == 0) {
                const float4 neg = make_float4(-1.f, -1.f, -1.f, -1.f);
                md[0] = neg;
                md[1] = neg;
            }
        }
    }
}

// ---------------------------------------------------------------------------
extern "C" void kernel_launch(void* const* d_in, const int* in_sizes, int n_in,
                              void* d_out, int out_size) {
    const float* x   = (const float*)d_in[0];   // [4,1024,2048] f32
    const float* wts = (const float*)d_in[1];   // [4,1024,4]    f32
    const int*   ind = (const int*)  d_in[2];   // [4,1024,4]    i32
    float* out = (float*)d_out;

    dispatch_kernel<<<NB, THREADS>>>(x, wts, ind, out);
}